// round 14
// baseline (speedup 1.0000x reference)
#include <cuda_runtime.h>
#include <cuda_fp16.h>
#include <math.h>
#include <stdint.h>

// ---- fixed problem shape (B=1) ----
#define T_      3
#define RES_    24
#define HW_     576
#define THW_    1728
#define DIM_    768
#define HEADS_  16
#define DH_     48
#define EMB_    1024
#define MLP_    3072
#define FUSEDN_ 5376
#define QKVN_   2304
#define QKN_    1536         // g_fused row: q|k fp32
#define VOFF_   1536
#define NBR_    75
#define KFIN_   3840         // 768 + 3072

// ---- scratch ----
__device__ __align__(16) float  g_mod[T_ * 2 * DIM_];
__device__ __align__(16) float  g_stats[2 * THW_];           // [sum | sumsq]
__device__ __align__(16) __half g_h[THW_ * DIM_];            // LN-mod activations
__device__ __align__(16) float  g_fused[THW_ * QKN_];        // q|k (fp32)
__device__ __align__(16) __half g_kvh[THW_ * 1536];          // [k(rope'd) | v] fp16
__device__ __align__(16) __half g_afin[THW_ * KFIN_];        // [xa | silu(mlp_h)]
__device__ __align__(16) __half g_WF[DIM_ * FUSEDN_];        // W_fused (half, [K][N])
__device__ __align__(16) __half g_WFin[KFIN_ * DIM_];        // [Wout;Wmlp] (half, [K][N])

__device__ __forceinline__ uint32_t smem_u32(const void* p) {
    uint32_t a;
    asm("{ .reg .u64 t; cvta.to.shared.u64 t, %1; cvt.u32.u64 %0, t; }" : "=r"(a) : "l"(p));
    return a;
}
__device__ __forceinline__ void cp16(uint32_t dst, const void* src, int srcsize) {
    asm volatile("cp.async.cg.shared.global [%0], [%1], 16, %2;"
                 :: "r"(dst), "l"(src), "r"(srcsize));
}
#define CP_COMMIT() asm volatile("cp.async.commit_group;" ::: "memory")
#define CP_WAIT0()  asm volatile("cp.async.wait_group 0;" ::: "memory")
#define CP_WAIT1()  asm volatile("cp.async.wait_group 1;" ::: "memory")
#define CP_WAIT2()  asm volatile("cp.async.wait_group 2;" ::: "memory")

__device__ __forceinline__ void ldsm_x4(uint32_t& r0, uint32_t& r1, uint32_t& r2, uint32_t& r3,
                                        uint32_t addr) {
    asm volatile("ldmatrix.sync.aligned.m8n8.x4.shared.b16 {%0,%1,%2,%3}, [%4];"
                 : "=r"(r0), "=r"(r1), "=r"(r2), "=r"(r3) : "r"(addr));
}
__device__ __forceinline__ void ldsm_x4t(uint32_t& r0, uint32_t& r1, uint32_t& r2, uint32_t& r3,
                                         uint32_t addr) {
    asm volatile("ldmatrix.sync.aligned.m8n8.x4.trans.shared.b16 {%0,%1,%2,%3}, [%4];"
                 : "=r"(r0), "=r"(r1), "=r"(r2), "=r"(r3) : "r"(addr));
}
__device__ __forceinline__ void mma_f16(float* c, const uint32_t* a, const uint32_t* b) {
    asm volatile(
        "mma.sync.aligned.m16n8k16.row.col.f32.f16.f16.f32 "
        "{%0,%1,%2,%3}, {%4,%5,%6,%7}, {%8,%9}, {%0,%1,%2,%3};"
        : "+f"(c[0]), "+f"(c[1]), "+f"(c[2]), "+f"(c[3])
        : "r"(a[0]), "r"(a[1]), "r"(a[2]), "r"(a[3]), "r"(b[0]), "r"(b[1]));
}

#define ROWH 40    // A smem row: 32 halfs + 8 pad
#define ROWB 136   // B smem row: 128 halfs + 8 pad

// ========== pipelined fp16 GEMM, 3-stage cp.async, B [K][N] via ldmatrix.trans ==
template<int MT, int EPI>
__global__ void __launch_bounds__(256, 2) k_gemm(
        const __half* __restrict__ A, int lda,
        const __half* __restrict__ B, int ldb, int Ktot,
        const float* __restrict__ bias,
        float* __restrict__ Cq, __half* __restrict__ kvh, __half* __restrict__ afin,
        float* __restrict__ outp, const float* __restrict__ x) {
    extern __shared__ __half smh[];
    const int AROWS = 32 * MT;
    const int ATILE = AROWS * ROWH;
    const int BTILE = 32 * ROWB;
    uint32_t s0 = smem_u32(smh);

    int tid = threadIdx.x;
    int wid = tid >> 5, lane = tid & 31;
    int wm = wid >> 2, wn = wid & 3;
    int lr = lane >> 2, lc = lane & 3;
    int m0 = blockIdx.y * AROWS, n0 = blockIdx.x * 128;

    float acc[MT][4][4];
    #pragma unroll
    for (int i = 0; i < MT; i++)
        #pragma unroll
        for (int j = 0; j < 4; j++)
            #pragma unroll
            for (int r = 0; r < 4; r++) acc[i][j][r] = 0.f;

    int nch = Ktot >> 5;

    auto issue = [&](int ch) {
        int buf = ch % 3;
        int k0 = ch << 5;
        uint32_t baseA = s0 + (uint32_t)(buf * ATILE) * 2u;
        uint32_t baseB = s0 + (uint32_t)((3 * ATILE) + buf * BTILE) * 2u;
        #pragma unroll
        for (int it = 0; it < (AROWS * 4 + 255) / 256; it++) {
            int idx = it * 256 + tid;
            if (idx < AROWS * 4) {
                int row = idx >> 2, g = idx & 3;
                int m = m0 + row;
                const __half* pa = A + (size_t)(m < THW_ ? m : THW_ - 1) * lda + k0 + g * 8;
                cp16(baseA + (uint32_t)(row * ROWH + g * 8) * 2u, pa, (m < THW_) ? 16 : 0);
            }
        }
        #pragma unroll
        for (int it = 0; it < 2; it++) {
            int idx = it * 256 + tid;
            int row = idx >> 4, g = idx & 15;
            const __half* pb = B + (size_t)(k0 + row) * ldb + n0 + g * 8;
            cp16(baseB + (uint32_t)(row * ROWB + g * 8) * 2u, pb, 16);
        }
        CP_COMMIT();
    };

    issue(0);
    if (nch > 1) issue(1);
    for (int ch = 0; ch < nch; ch++) {
        if (ch + 2 < nch)      { issue(ch + 2); CP_WAIT2(); }
        else if (ch + 1 < nch) CP_WAIT1();
        else                   CP_WAIT0();
        __syncthreads();
        int buf = ch % 3;
        uint32_t baseA = s0 + (uint32_t)(buf * ATILE) * 2u;
        uint32_t baseB = s0 + (uint32_t)((3 * ATILE) + buf * BTILE) * 2u;

        #pragma unroll
        for (int ks = 0; ks < 2; ks++) {
            uint32_t af[MT][4], bf[4][2];
            #pragma unroll
            for (int mt = 0; mt < MT; mt++) {
                int r = wm * (16 * MT) + mt * 16 + (lane & 15);
                uint32_t addr = baseA + (uint32_t)(r * ROWH + ks * 16 + (lane >> 4) * 8) * 2u;
                ldsm_x4(af[mt][0], af[mt][1], af[mt][2], af[mt][3], addr);
            }
            #pragma unroll
            for (int np = 0; np < 2; np++) {
                int q = lane >> 3;
                int kr = ks * 16 + (q & 1) * 8 + (lane & 7);
                int nc = wn * 32 + (np * 2 + (q >> 1)) * 8;
                uint32_t addr = baseB + (uint32_t)(kr * ROWB + nc) * 2u;
                ldsm_x4t(bf[np * 2][0], bf[np * 2][1], bf[np * 2 + 1][0], bf[np * 2 + 1][1], addr);
            }
            #pragma unroll
            for (int mt = 0; mt < MT; mt++)
                #pragma unroll
                for (int nt = 0; nt < 4; nt++)
                    mma_f16(acc[mt][nt], af[mt], bf[nt]);
        }
        __syncthreads();
    }

    if (EPI == 0) {
        int kind = (n0 >= QKVN_) ? 2 : (n0 >= VOFF_) ? 1 : 0;
        #pragma unroll
        for (int mt = 0; mt < MT; mt++) {
            #pragma unroll
            for (int hf = 0; hf < 2; hf++) {
                int mrow = m0 + wm * (16 * MT) + mt * 16 + lr + hf * 8;
                if (mrow >= THW_) continue;
                #pragma unroll
                for (int nt = 0; nt < 4; nt++) {
                    int n = n0 + wn * 32 + nt * 8 + 2 * lc;
                    float v0 = acc[mt][nt][hf * 2 + 0] + bias[n];
                    float v1 = acc[mt][nt][hf * 2 + 1] + bias[n + 1];
                    if (kind == 2) {
                        v0 = v0 / (1.f + expf(-v0));
                        v1 = v1 / (1.f + expf(-v1));
                        *(__half2*)(afin + (size_t)mrow * KFIN_ + 768 + (n - QKVN_)) =
                            __floats2half2_rn(v0, v1);
                    } else if (kind == 1) {
                        *(__half2*)(kvh + (size_t)mrow * 1536 + 768 + (n - VOFF_)) =
                            __floats2half2_rn(v0, v1);
                    } else {
                        *(float2*)(Cq + (size_t)mrow * QKN_ + n) = make_float2(v0, v1);
                    }
                }
            }
        }
    } else {
        const int PITCH = AROWS + 1;
        float* st = (float*)smh;
        #pragma unroll
        for (int mt = 0; mt < MT; mt++) {
            #pragma unroll
            for (int hf = 0; hf < 2; hf++) {
                int ml = wm * (16 * MT) + mt * 16 + lr + hf * 8;
                #pragma unroll
                for (int nt = 0; nt < 4; nt++) {
                    int nl = wn * 32 + nt * 8 + 2 * lc;
                    st[nl * PITCH + ml]       = acc[mt][nt][hf * 2 + 0];
                    st[(nl + 1) * PITCH + ml] = acc[mt][nt][hf * 2 + 1];
                }
            }
        }
        __syncthreads();
        int t = m0 / HW_, hw0 = m0 % HW_;
        int nr = tid >> 1, mh = (tid & 1) * (AROWS / 2);
        int n = n0 + nr;
        float bb = bias[n];
        const float* xrow = x + ((size_t)t * DIM_ + n) * HW_ + hw0 + mh;
        float* orow = outp + ((size_t)t * DIM_ + n) * HW_ + hw0 + mh;
        #pragma unroll
        for (int i = 0; i < AROWS / 8; i++) {
            float4 xs = *(const float4*)(xrow + i * 4);
            float4 o;
            o.x = st[nr * PITCH + mh + i * 4 + 0] + bb + xs.x;
            o.y = st[nr * PITCH + mh + i * 4 + 1] + bb + xs.y;
            o.z = st[nr * PITCH + mh + i * 4 + 2] + bb + xs.z;
            o.w = st[nr * PITCH + mh + i * 4 + 3] + bb + xs.w;
            *(float4*)(orow + i * 4) = o;
        }
    }
}

// ===================== merged prologue: cvtWF | cvtWFin | mod | stats ==========
#define NB_CVT1  2016
#define NB_CVT2  1440
#define NB_MOD   18
#define NB_STATS 144
#define NB_PRO   (NB_CVT1 + NB_CVT2 + NB_MOD + NB_STATS)

__global__ void k_prolog(const float* __restrict__ W_fused,
                         const float* __restrict__ Wout, const float* __restrict__ Wmlp,
                         const float* __restrict__ emb, const float* __restrict__ w_mod,
                         const float* __restrict__ b_mod, const float* __restrict__ x) {
    int b = blockIdx.x;
    if (b < NB_CVT1) {
        int i = b * 256 + threadIdx.x;
        float4 a = *(const float4*)(W_fused + (size_t)i * 8);
        float4 c = *(const float4*)(W_fused + (size_t)i * 8 + 4);
        __half2 h[4] = { __floats2half2_rn(a.x, a.y), __floats2half2_rn(a.z, a.w),
                         __floats2half2_rn(c.x, c.y), __floats2half2_rn(c.z, c.w) };
        *(uint2*)(g_WF + (size_t)i * 8)     = *(uint2*)&h[0];
        *(uint2*)(g_WF + (size_t)i * 8 + 4) = *(uint2*)&h[2];
    } else if (b < NB_CVT1 + NB_CVT2) {
        int i = (b - NB_CVT1) * 256 + threadIdx.x;
        const int N1 = DIM_ * DIM_ / 8;
        const float* src = (i < N1) ? (Wout + (size_t)i * 8)
                                    : (Wmlp + (size_t)(i - N1) * 8);
        float4 a = *(const float4*)(src);
        float4 c = *(const float4*)(src + 4);
        __half2 h[4] = { __floats2half2_rn(a.x, a.y), __floats2half2_rn(a.z, a.w),
                         __floats2half2_rn(c.x, c.y), __floats2half2_rn(c.z, c.w) };
        *(uint2*)(g_WFin + (size_t)i * 8)     = *(uint2*)&h[0];
        *(uint2*)(g_WFin + (size_t)i * 8 + 4) = *(uint2*)&h[2];
    } else if (b < NB_CVT1 + NB_CVT2 + NB_MOD) {
        int bi = b - NB_CVT1 - NB_CVT2;
        int t = bi / 6, col = (bi % 6) * 256 + threadIdx.x;
        __shared__ float se[EMB_];
        for (int k = threadIdx.x; k < EMB_; k += 256) {
            float e = emb[t * EMB_ + k];
            se[k] = e / (1.f + expf(-e));
        }
        __syncthreads();
        float acc = 0.f;
        #pragma unroll 8
        for (int k = 0; k < EMB_; k++) acc += se[k] * w_mod[k * (2 * DIM_) + col];
        g_mod[t * (2 * DIM_) + col] = acc + b_mod[col];
    } else {
        int bi = b - NB_CVT1 - NB_CVT2 - NB_MOD;
        int t = bi / 48, d0 = (bi % 48) * 16;
        #pragma unroll
        for (int rep = 0; rep < 3; rep++) {
            int hw = threadIdx.x + rep * 256;
            if (hw < HW_) {
                float s = 0.f, q = 0.f;
                const float* xp = x + ((size_t)t * DIM_ + d0) * HW_ + hw;
                #pragma unroll
                for (int i = 0; i < 16; i++) {
                    float v = xp[(size_t)i * HW_];
                    s += v; q += v * v;
                }
                atomicAdd(&g_stats[t * HW_ + hw], s);
                atomicAdd(&g_stats[THW_ + t * HW_ + hw], q);
            }
        }
    }
}

__global__ void k_applyT(const float* __restrict__ x) {
    __shared__ float tile[32][33];
    int t = blockIdx.z;
    int hw0 = blockIdx.x * 32, d0 = blockIdx.y * 32;
    int tx = threadIdx.x, ty = threadIdx.y;
    #pragma unroll
    for (int i = 0; i < 4; i++)
        tile[ty + i * 8][tx] = x[((size_t)t * DIM_ + d0 + ty + i * 8) * HW_ + hw0 + tx];
    __syncthreads();
    int d = d0 + tx;
    float sc = 1.f + g_mod[t * 1536 + d];
    float sh = g_mod[t * 1536 + 768 + d];
    #pragma unroll
    for (int i = 0; i < 4; i++) {
        int hw = hw0 + ty + i * 8;
        int p = t * HW_ + hw;
        float sum = g_stats[p], sq = g_stats[THW_ + p];
        float mean = sum * (1.f / 768.f);
        float var = sq * (1.f / 768.f) - mean * mean;
        float rinv = rsqrtf(var + 1e-5f);
        g_h[(size_t)p * DIM_ + d] = __float2half((tile[tx][ty + i * 8] - mean) * rinv * sc + sh);
    }
}

// ============ q/k LN + RoPE, single pass with interleaved q/k chains ============
__global__ void k_qk(const float* __restrict__ qn_w, const float* __restrict__ qn_b,
                     const float* __restrict__ kn_w, const float* __restrict__ kn_b) {
    int gw = (blockIdx.x * blockDim.x + threadIdx.x) >> 5;
    int lane = threadIdx.x & 31;
    if (gw >= THW_ * HEADS_) return;
    int p = gw / HEADS_, head = gw % HEADS_;
    int t = p / HW_, hw = p % HW_;
    int hh = hw / RES_, ww = hw % RES_;
    float coord = (lane < 8) ? (float)t : (lane < 16) ? (float)hh : (float)ww;
    float inv = exp2f(-1.66096404744368f * (float)(lane & 7));
    float ang = coord * inv;
    float c = cosf(ang), s = sinf(ang);

    float* baseq = g_fused + (size_t)p * QKN_ + head * DH_;
    float* basek = baseq + 768;
    float qx1 = 0.f, qx2 = 0.f, kx1 = 0.f, kx2 = 0.f;
    if (lane < 24) {
        float2 qv = *(const float2*)(baseq + 2 * lane);
        float2 kv = *(const float2*)(basek + 2 * lane);
        qx1 = qv.x; qx2 = qv.y; kx1 = kv.x; kx2 = kv.y;
    }
    float qs = qx1 + qx2, qq = qx1 * qx1 + qx2 * qx2;
    float ks = kx1 + kx2, kq = kx1 * kx1 + kx2 * kx2;
    #pragma unroll
    for (int o = 16; o; o >>= 1) {
        qs += __shfl_xor_sync(0xffffffffu, qs, o);
        ks += __shfl_xor_sync(0xffffffffu, ks, o);
        qq += __shfl_xor_sync(0xffffffffu, qq, o);
        kq += __shfl_xor_sync(0xffffffffu, kq, o);
    }
    float qmean = qs * (1.f / 48.f), kmean = ks * (1.f / 48.f);
    float qrinv = rsqrtf(qq * (1.f / 48.f) - qmean * qmean + 1e-5f);
    float krinv = rsqrtf(kq * (1.f / 48.f) - kmean * kmean + 1e-5f);
    if (lane < 24) {
        float qw1 = qn_w[2 * lane], qw2 = qn_w[2 * lane + 1];
        float qb1 = qn_b[2 * lane], qb2 = qn_b[2 * lane + 1];
        float kw1 = kn_w[2 * lane], kw2 = kn_w[2 * lane + 1];
        float kb1 = kn_b[2 * lane], kb2 = kn_b[2 * lane + 1];
        float qy1 = (qx1 - qmean) * qrinv * qw1 + qb1;
        float qy2 = (qx2 - qmean) * qrinv * qw2 + qb2;
        float ky1 = (kx1 - kmean) * krinv * kw1 + kb1;
        float ky2 = (kx2 - kmean) * krinv * kw2 + kb2;
        float qo1 = (qy1 * c - qy2 * s) * 0.14433756729740643f;
        float qo2 = (qy1 * s + qy2 * c) * 0.14433756729740643f;
        float ko1 = ky1 * c - ky2 * s;
        float ko2 = ky1 * s + ky2 * c;
        baseq[2 * lane] = qo1; baseq[2 * lane + 1] = qo2;
        *(__half2*)(g_kvh + (size_t)p * 1536 + head * DH_ + 2 * lane) =
            __floats2half2_rn(ko1, ko2);
    }
}

// ============ attention: smem-tiled strips (t,h, 8 w) x head ============
// Block: 256 thr. Stage union neighborhood (3 x 5 x 12 positions) of K and V for
// one head into smem, then 8 warps each run one query (group-of-8 structure).
#define TW_ 12
#define NPOS_ 180            // 3*5*12
__global__ void __launch_bounds__(256) k_attn() {
    __shared__ __half kT[NPOS_ * DH_];     // 17280 B
    __shared__ __half vT[NPOS_ * DH_];     // 17280 B
    __shared__ float ssc[8][80];

    int sidx = blockIdx.x;                 // 216 strips
    int head = blockIdx.y;
    int t = sidx / 72;
    int rem = sidx % 72;
    int h = rem / 3;
    int w0 = (rem % 3) * 8;
    int hs0 = min(max(h - 2, 0), RES_ - 5);
    int ws0 = min(max(w0 - 2, 0), RES_ - 5);   // strip tile origin (w)

    int tid = threadIdx.x;
    // cooperative load: K then V, 6 granules (8 halfs) per position
    for (int i = tid; i < 2 * NPOS_ * 6; i += 256) {
        int tensor = i >= NPOS_ * 6;
        int j = tensor ? i - NPOS_ * 6 : i;
        int pos = j / 6, g = j % 6;
        int a = pos / 60, r = pos % 60, cc = r / TW_, wr = r % TW_;
        if (ws0 + wr < RES_) {
            int p = (a * RES_ + hs0 + cc) * RES_ + ws0 + wr;
            const __half* src = g_kvh + (size_t)p * 1536 + (tensor ? 768 : 0)
                                + head * DH_ + g * 8;
            __half* dst = (tensor ? vT : kT) + pos * DH_ + g * 8;
            *(uint4*)dst = *(const uint4*)src;
        }
    }
    __syncthreads();

    int wid = tid >> 5, lane = tid & 31;
    int grp = lane >> 3, gl = lane & 7;
    int w = w0 + wid;                      // this warp's query w
    int p = (t * RES_ + h) * RES_ + w;
    int ws = min(max(w - 2, 0), RES_ - 5);
    int woff = ws - ws0;                   // 0..7
    float* sc = ssc[wid];

    float qr[8];
    if (gl < 6) {
        float4 qv0 = *(const float4*)(g_fused + (size_t)p * QKN_ + head * DH_ + gl * 8);
        float4 qv1 = *(const float4*)(g_fused + (size_t)p * QKN_ + head * DH_ + gl * 8 + 4);
        qr[0] = qv0.x; qr[1] = qv0.y; qr[2] = qv0.z; qr[3] = qv0.w;
        qr[4] = qv1.x; qr[5] = qv1.y; qr[6] = qv1.z; qr[7] = qv1.w;
    }

    #pragma unroll 4
    for (int jb = 0; jb < 19; jb++) {
        int j = jb * 4 + grp;
        float partial = 0.f;
        if (j < NBR_ && gl < 6) {
            int a = j / 25, r = j % 25, cc = r / 5, e = r % 5;
            int pos = (a * 5 + cc) * TW_ + woff + e;
            uint4 kv = *(const uint4*)(kT + pos * DH_ + gl * 8);
            float2 f0 = __half22float2(*(__half2*)&kv.x);
            float2 f1 = __half22float2(*(__half2*)&kv.y);
            float2 f2 = __half22float2(*(__half2*)&kv.z);
            float2 f3 = __half22float2(*(__half2*)&kv.w);
            partial = qr[0] * f0.x + qr[1] * f0.y + qr[2] * f1.x + qr[3] * f1.y
                    + qr[4] * f2.x + qr[5] * f2.y + qr[6] * f3.x + qr[7] * f3.y;
        }
        partial += __shfl_xor_sync(0xffffffffu, partial, 1);
        partial += __shfl_xor_sync(0xffffffffu, partial, 2);
        partial += __shfl_xor_sync(0xffffffffu, partial, 4);
        if (gl == 0 && j < NBR_) sc[j] = partial;
    }
    __syncwarp();

    float m = -1e30f;
    for (int j = lane; j < NBR_; j += 32) m = fmaxf(m, sc[j]);
    #pragma unroll
    for (int o = 16; o; o >>= 1) m = fmaxf(m, __shfl_xor_sync(0xffffffffu, m, o));
    float sum = 0.f;
    for (int j = lane; j < NBR_; j += 32) {
        float e = __expf(sc[j] - m);
        sc[j] = e; sum += e;
    }
    #pragma unroll
    for (int o = 16; o; o >>= 1) sum += __shfl_xor_sync(0xffffffffu, sum, o);
    float rs = 1.f / sum;
    for (int j = lane; j < NBR_; j += 32) sc[j] *= rs;
    __syncwarp();

    float vacc[8] = {0.f, 0.f, 0.f, 0.f, 0.f, 0.f, 0.f, 0.f};
    #pragma unroll 4
    for (int jb = 0; jb < 19; jb++) {
        int j = jb * 4 + grp;
        if (j < NBR_ && gl < 6) {
            int a = j / 25, r = j % 25, cc = r / 5, e = r % 5;
            int pos = (a * 5 + cc) * TW_ + woff + e;
            float pj = sc[j];
            uint4 vv = *(const uint4*)(vT + pos * DH_ + gl * 8);
            float2 f0 = __half22float2(*(__half2*)&vv.x);
            float2 f1 = __half22float2(*(__half2*)&vv.y);
            float2 f2 = __half22float2(*(__half2*)&vv.z);
            float2 f3 = __half22float2(*(__half2*)&vv.w);
            vacc[0] += pj * f0.x; vacc[1] += pj * f0.y;
            vacc[2] += pj * f1.x; vacc[3] += pj * f1.y;
            vacc[4] += pj * f2.x; vacc[5] += pj * f2.y;
            vacc[6] += pj * f3.x; vacc[7] += pj * f3.y;
        }
    }
    #pragma unroll
    for (int d = 0; d < 8; d++) {
        vacc[d] += __shfl_xor_sync(0xffffffffu, vacc[d], 8);
        vacc[d] += __shfl_xor_sync(0xffffffffu, vacc[d], 16);
    }
    if (grp == 0 && gl < 6) {
        __half2 h0 = __floats2half2_rn(vacc[0], vacc[1]);
        __half2 h1 = __floats2half2_rn(vacc[2], vacc[3]);
        __half2 h2 = __floats2half2_rn(vacc[4], vacc[5]);
        __half2 h3 = __floats2half2_rn(vacc[6], vacc[7]);
        uint4 o = make_uint4(*(uint32_t*)&h0, *(uint32_t*)&h1,
                             *(uint32_t*)&h2, *(uint32_t*)&h3);
        *(uint4*)(g_afin + (size_t)p * KFIN_ + head * DH_ + gl * 8) = o;
    }
}

// ===================== launch =====================
extern "C" void kernel_launch(void* const* d_in, const int* in_sizes, int n_in,
                              void* d_out, int out_size) {
    const float* x       = (const float*)d_in[0];
    const float* emb     = (const float*)d_in[1];
    const float* w_mod   = (const float*)d_in[2];
    const float* b_mod   = (const float*)d_in[3];
    const float* qn_w    = (const float*)d_in[4];
    const float* qn_b    = (const float*)d_in[5];
    const float* kn_w    = (const float*)d_in[6];
    const float* kn_b    = (const float*)d_in[7];
    const float* W_fused = (const float*)d_in[8];
    const float* b_fused = (const float*)d_in[9];
    const float* W_out   = (const float*)d_in[10];
    const float* W_mlp   = (const float*)d_in[11];
    const float* b_mlp   = (const float*)d_in[12];
    float* out = (float*)d_out;

    __half* WF;    cudaGetSymbolAddress((void**)&WF, g_WF);
    __half* WFin;  cudaGetSymbolAddress((void**)&WFin, g_WFin);
    __half* gh;    cudaGetSymbolAddress((void**)&gh, g_h);
    float* gfused; cudaGetSymbolAddress((void**)&gfused, g_fused);
    __half* gkvh;  cudaGetSymbolAddress((void**)&gkvh, g_kvh);
    __half* gafin; cudaGetSymbolAddress((void**)&gafin, g_afin);
    float* gstats; cudaGetSymbolAddress((void**)&gstats, g_stats);

    const int smem1 = 3 * (128 * ROWH + 32 * ROWB) * 2;
    const int g2pipe = 3 * (32 * ROWH + 32 * ROWB) * 2;
    const int g2epi  = 128 * 33 * 4;
    const int smem2 = (g2pipe > g2epi) ? g2pipe : g2epi;
    cudaFuncSetAttribute(k_gemm<4, 0>, cudaFuncAttributeMaxDynamicSharedMemorySize, smem1);
    cudaFuncSetAttribute(k_gemm<1, 1>, cudaFuncAttributeMaxDynamicSharedMemorySize, smem2);

    cudaMemsetAsync(gstats, 0, 2 * THW_ * sizeof(float));
    k_prolog<<<NB_PRO, 256>>>(W_fused, W_out, W_mlp, emb, w_mod, b_mod, x);
    k_applyT<<<dim3(HW_ / 32, DIM_ / 32, T_), dim3(32, 8)>>>(x);
    // fused GEMM: 1728 x 5376, K=768 (q|k fp32, v half, silu(mlp) half)
    k_gemm<4, 0><<<dim3(FUSEDN_ / 128, 14), 256, smem1>>>(
        gh, DIM_, WF, FUSEDN_, DIM_, b_fused, gfused, gkvh, gafin, nullptr, nullptr);
    k_qk<<<(THW_ * HEADS_) / 8, 256>>>(qn_w, qn_b, kn_w, kn_b);
    // smem-tiled attention: 216 strips x 16 heads
    k_attn<<<dim3(216, HEADS_), 256>>>();
    // final GEMM: 1728 x 768, K=3840, MT=1 -> 324 CTAs
    k_gemm<1, 1><<<dim3(DIM_ / 128, THW_ / 32), 256, smem2>>>(
        gafin, KFIN_, WFin, DIM_, KFIN_, b_mlp, nullptr, nullptr, nullptr, out, x);
}

// round 15
// speedup vs baseline: 1.7365x; 1.7365x over previous
#include <cuda_runtime.h>
#include <cuda_fp16.h>
#include <math.h>
#include <stdint.h>

// ---- fixed problem shape (B=1) ----
#define T_      3
#define RES_    24
#define HW_     576
#define THW_    1728
#define DIM_    768
#define HEADS_  16
#define DH_     48
#define EMB_    1024
#define MLP_    3072
#define FUSEDN_ 5376
#define QKVN_   2304
#define QKN_    1536         // g_fused row: q|k fp32
#define VOFF_   1536
#define NBR_    75
#define KFIN_   3840         // 768 + 3072

// ---- scratch ----
__device__ __align__(16) float  g_mod[T_ * 2 * DIM_];
__device__ __align__(16) float  g_stats[2 * THW_];           // [sum | sumsq]
__device__ __align__(16) __half g_h[THW_ * DIM_];            // LN-mod activations
__device__ __align__(16) float  g_fused[THW_ * QKN_];        // q|k (fp32)
__device__ __align__(16) __half g_kvh[THW_ * 1536];          // [k(rope'd) | v] fp16
__device__ __align__(16) __half g_afin[THW_ * KFIN_];        // [xa | silu(mlp_h)]
__device__ __align__(16) __half g_WF[DIM_ * FUSEDN_];        // W_fused (half, [K][N])
__device__ __align__(16) __half g_WFin[KFIN_ * DIM_];        // [Wout;Wmlp] (half, [K][N])

__device__ __forceinline__ uint32_t smem_u32(const void* p) {
    uint32_t a;
    asm("{ .reg .u64 t; cvta.to.shared.u64 t, %1; cvt.u32.u64 %0, t; }" : "=r"(a) : "l"(p));
    return a;
}
__device__ __forceinline__ void cp16(uint32_t dst, const void* src, int srcsize) {
    asm volatile("cp.async.cg.shared.global [%0], [%1], 16, %2;"
                 :: "r"(dst), "l"(src), "r"(srcsize));
}
#define CP_COMMIT() asm volatile("cp.async.commit_group;" ::: "memory")
#define CP_WAIT0()  asm volatile("cp.async.wait_group 0;" ::: "memory")
#define CP_WAIT1()  asm volatile("cp.async.wait_group 1;" ::: "memory")
#define CP_WAIT2()  asm volatile("cp.async.wait_group 2;" ::: "memory")

__device__ __forceinline__ void ldsm_x4(uint32_t& r0, uint32_t& r1, uint32_t& r2, uint32_t& r3,
                                        uint32_t addr) {
    asm volatile("ldmatrix.sync.aligned.m8n8.x4.shared.b16 {%0,%1,%2,%3}, [%4];"
                 : "=r"(r0), "=r"(r1), "=r"(r2), "=r"(r3) : "r"(addr));
}
__device__ __forceinline__ void ldsm_x4t(uint32_t& r0, uint32_t& r1, uint32_t& r2, uint32_t& r3,
                                         uint32_t addr) {
    asm volatile("ldmatrix.sync.aligned.m8n8.x4.trans.shared.b16 {%0,%1,%2,%3}, [%4];"
                 : "=r"(r0), "=r"(r1), "=r"(r2), "=r"(r3) : "r"(addr));
}
__device__ __forceinline__ void mma_f16(float* c, const uint32_t* a, const uint32_t* b) {
    asm volatile(
        "mma.sync.aligned.m16n8k16.row.col.f32.f16.f16.f32 "
        "{%0,%1,%2,%3}, {%4,%5,%6,%7}, {%8,%9}, {%0,%1,%2,%3};"
        : "+f"(c[0]), "+f"(c[1]), "+f"(c[2]), "+f"(c[3])
        : "r"(a[0]), "r"(a[1]), "r"(a[2]), "r"(a[3]), "r"(b[0]), "r"(b[1]));
}

#define ROWH 40    // A smem row: 32 halfs + 8 pad
#define ROWB 136   // B smem row: 128 halfs + 8 pad

// ========== pipelined fp16 GEMM, 3-stage cp.async, B [K][N] via ldmatrix.trans ==
template<int MT, int EPI>
__global__ void __launch_bounds__(256, 2) k_gemm(
        const __half* __restrict__ A, int lda,
        const __half* __restrict__ B, int ldb, int Ktot,
        const float* __restrict__ bias,
        float* __restrict__ Cq, __half* __restrict__ kvh, __half* __restrict__ afin,
        float* __restrict__ outp, const float* __restrict__ x) {
    extern __shared__ __half smh[];
    const int AROWS = 32 * MT;
    const int ATILE = AROWS * ROWH;
    const int BTILE = 32 * ROWB;
    uint32_t s0 = smem_u32(smh);

    int tid = threadIdx.x;
    int wid = tid >> 5, lane = tid & 31;
    int wm = wid >> 2, wn = wid & 3;
    int lr = lane >> 2, lc = lane & 3;
    int m0 = blockIdx.y * AROWS, n0 = blockIdx.x * 128;

    float acc[MT][4][4];
    #pragma unroll
    for (int i = 0; i < MT; i++)
        #pragma unroll
        for (int j = 0; j < 4; j++)
            #pragma unroll
            for (int r = 0; r < 4; r++) acc[i][j][r] = 0.f;

    int nch = Ktot >> 5;

    auto issue = [&](int ch) {
        int buf = ch % 3;
        int k0 = ch << 5;
        uint32_t baseA = s0 + (uint32_t)(buf * ATILE) * 2u;
        uint32_t baseB = s0 + (uint32_t)((3 * ATILE) + buf * BTILE) * 2u;
        #pragma unroll
        for (int it = 0; it < (AROWS * 4 + 255) / 256; it++) {
            int idx = it * 256 + tid;
            if (idx < AROWS * 4) {
                int row = idx >> 2, g = idx & 3;
                int m = m0 + row;
                const __half* pa = A + (size_t)(m < THW_ ? m : THW_ - 1) * lda + k0 + g * 8;
                cp16(baseA + (uint32_t)(row * ROWH + g * 8) * 2u, pa, (m < THW_) ? 16 : 0);
            }
        }
        #pragma unroll
        for (int it = 0; it < 2; it++) {
            int idx = it * 256 + tid;
            int row = idx >> 4, g = idx & 15;
            const __half* pb = B + (size_t)(k0 + row) * ldb + n0 + g * 8;
            cp16(baseB + (uint32_t)(row * ROWB + g * 8) * 2u, pb, 16);
        }
        CP_COMMIT();
    };

    issue(0);
    if (nch > 1) issue(1);
    for (int ch = 0; ch < nch; ch++) {
        if (ch + 2 < nch)      { issue(ch + 2); CP_WAIT2(); }
        else if (ch + 1 < nch) CP_WAIT1();
        else                   CP_WAIT0();
        __syncthreads();
        int buf = ch % 3;
        uint32_t baseA = s0 + (uint32_t)(buf * ATILE) * 2u;
        uint32_t baseB = s0 + (uint32_t)((3 * ATILE) + buf * BTILE) * 2u;

        #pragma unroll
        for (int ks = 0; ks < 2; ks++) {
            uint32_t af[MT][4], bf[4][2];
            #pragma unroll
            for (int mt = 0; mt < MT; mt++) {
                int r = wm * (16 * MT) + mt * 16 + (lane & 15);
                uint32_t addr = baseA + (uint32_t)(r * ROWH + ks * 16 + (lane >> 4) * 8) * 2u;
                ldsm_x4(af[mt][0], af[mt][1], af[mt][2], af[mt][3], addr);
            }
            #pragma unroll
            for (int np = 0; np < 2; np++) {
                int q = lane >> 3;
                int kr = ks * 16 + (q & 1) * 8 + (lane & 7);
                int nc = wn * 32 + (np * 2 + (q >> 1)) * 8;
                uint32_t addr = baseB + (uint32_t)(kr * ROWB + nc) * 2u;
                ldsm_x4t(bf[np * 2][0], bf[np * 2][1], bf[np * 2 + 1][0], bf[np * 2 + 1][1], addr);
            }
            #pragma unroll
            for (int mt = 0; mt < MT; mt++)
                #pragma unroll
                for (int nt = 0; nt < 4; nt++)
                    mma_f16(acc[mt][nt], af[mt], bf[nt]);
        }
        __syncthreads();
    }

    if (EPI == 0) {
        int kind = (n0 >= QKVN_) ? 2 : (n0 >= VOFF_) ? 1 : 0;
        #pragma unroll
        for (int mt = 0; mt < MT; mt++) {
            #pragma unroll
            for (int hf = 0; hf < 2; hf++) {
                int mrow = m0 + wm * (16 * MT) + mt * 16 + lr + hf * 8;
                if (mrow >= THW_) continue;
                #pragma unroll
                for (int nt = 0; nt < 4; nt++) {
                    int n = n0 + wn * 32 + nt * 8 + 2 * lc;
                    float v0 = acc[mt][nt][hf * 2 + 0] + bias[n];
                    float v1 = acc[mt][nt][hf * 2 + 1] + bias[n + 1];
                    if (kind == 2) {
                        v0 = v0 / (1.f + expf(-v0));
                        v1 = v1 / (1.f + expf(-v1));
                        *(__half2*)(afin + (size_t)mrow * KFIN_ + 768 + (n - QKVN_)) =
                            __floats2half2_rn(v0, v1);
                    } else if (kind == 1) {
                        *(__half2*)(kvh + (size_t)mrow * 1536 + 768 + (n - VOFF_)) =
                            __floats2half2_rn(v0, v1);
                    } else {
                        *(float2*)(Cq + (size_t)mrow * QKN_ + n) = make_float2(v0, v1);
                    }
                }
            }
        }
    } else {
        const int PITCH = AROWS + 1;
        float* st = (float*)smh;
        #pragma unroll
        for (int mt = 0; mt < MT; mt++) {
            #pragma unroll
            for (int hf = 0; hf < 2; hf++) {
                int ml = wm * (16 * MT) + mt * 16 + lr + hf * 8;
                #pragma unroll
                for (int nt = 0; nt < 4; nt++) {
                    int nl = wn * 32 + nt * 8 + 2 * lc;
                    st[nl * PITCH + ml]       = acc[mt][nt][hf * 2 + 0];
                    st[(nl + 1) * PITCH + ml] = acc[mt][nt][hf * 2 + 1];
                }
            }
        }
        __syncthreads();
        int t = m0 / HW_, hw0 = m0 % HW_;
        int nr = tid >> 1, mh = (tid & 1) * (AROWS / 2);
        int n = n0 + nr;
        float bb = bias[n];
        const float* xrow = x + ((size_t)t * DIM_ + n) * HW_ + hw0 + mh;
        float* orow = outp + ((size_t)t * DIM_ + n) * HW_ + hw0 + mh;
        #pragma unroll
        for (int i = 0; i < AROWS / 8; i++) {
            float4 xs = *(const float4*)(xrow + i * 4);
            float4 o;
            o.x = st[nr * PITCH + mh + i * 4 + 0] + bb + xs.x;
            o.y = st[nr * PITCH + mh + i * 4 + 1] + bb + xs.y;
            o.z = st[nr * PITCH + mh + i * 4 + 2] + bb + xs.z;
            o.w = st[nr * PITCH + mh + i * 4 + 3] + bb + xs.w;
            *(float4*)(orow + i * 4) = o;
        }
    }
}

// ===================== merged prologue: cvtWF | cvtWFin | mod | stats ==========
#define NB_CVT1  2016
#define NB_CVT2  1440
#define NB_MOD   18
#define NB_STATS 144
#define NB_PRO   (NB_CVT1 + NB_CVT2 + NB_MOD + NB_STATS)

__global__ void k_prolog(const float* __restrict__ W_fused,
                         const float* __restrict__ Wout, const float* __restrict__ Wmlp,
                         const float* __restrict__ emb, const float* __restrict__ w_mod,
                         const float* __restrict__ b_mod, const float* __restrict__ x) {
    int b = blockIdx.x;
    if (b < NB_CVT1) {
        int i = b * 256 + threadIdx.x;
        float4 a = *(const float4*)(W_fused + (size_t)i * 8);
        float4 c = *(const float4*)(W_fused + (size_t)i * 8 + 4);
        __half2 h[4] = { __floats2half2_rn(a.x, a.y), __floats2half2_rn(a.z, a.w),
                         __floats2half2_rn(c.x, c.y), __floats2half2_rn(c.z, c.w) };
        *(uint2*)(g_WF + (size_t)i * 8)     = *(uint2*)&h[0];
        *(uint2*)(g_WF + (size_t)i * 8 + 4) = *(uint2*)&h[2];
    } else if (b < NB_CVT1 + NB_CVT2) {
        int i = (b - NB_CVT1) * 256 + threadIdx.x;
        const int N1 = DIM_ * DIM_ / 8;
        const float* src = (i < N1) ? (Wout + (size_t)i * 8)
                                    : (Wmlp + (size_t)(i - N1) * 8);
        float4 a = *(const float4*)(src);
        float4 c = *(const float4*)(src + 4);
        __half2 h[4] = { __floats2half2_rn(a.x, a.y), __floats2half2_rn(a.z, a.w),
                         __floats2half2_rn(c.x, c.y), __floats2half2_rn(c.z, c.w) };
        *(uint2*)(g_WFin + (size_t)i * 8)     = *(uint2*)&h[0];
        *(uint2*)(g_WFin + (size_t)i * 8 + 4) = *(uint2*)&h[2];
    } else if (b < NB_CVT1 + NB_CVT2 + NB_MOD) {
        int bi = b - NB_CVT1 - NB_CVT2;
        int t = bi / 6, col = (bi % 6) * 256 + threadIdx.x;
        __shared__ float se[EMB_];
        for (int k = threadIdx.x; k < EMB_; k += 256) {
            float e = emb[t * EMB_ + k];
            se[k] = e / (1.f + expf(-e));
        }
        __syncthreads();
        float acc = 0.f;
        #pragma unroll 8
        for (int k = 0; k < EMB_; k++) acc += se[k] * w_mod[k * (2 * DIM_) + col];
        g_mod[t * (2 * DIM_) + col] = acc + b_mod[col];
    } else {
        int bi = b - NB_CVT1 - NB_CVT2 - NB_MOD;
        int t = bi / 48, d0 = (bi % 48) * 16;
        #pragma unroll
        for (int rep = 0; rep < 3; rep++) {
            int hw = threadIdx.x + rep * 256;
            if (hw < HW_) {
                float s = 0.f, q = 0.f;
                const float* xp = x + ((size_t)t * DIM_ + d0) * HW_ + hw;
                #pragma unroll
                for (int i = 0; i < 16; i++) {
                    float v = xp[(size_t)i * HW_];
                    s += v; q += v * v;
                }
                atomicAdd(&g_stats[t * HW_ + hw], s);
                atomicAdd(&g_stats[THW_ + t * HW_ + hw], q);
            }
        }
    }
}

__global__ void k_applyT(const float* __restrict__ x) {
    __shared__ float tile[32][33];
    int t = blockIdx.z;
    int hw0 = blockIdx.x * 32, d0 = blockIdx.y * 32;
    int tx = threadIdx.x, ty = threadIdx.y;
    #pragma unroll
    for (int i = 0; i < 4; i++)
        tile[ty + i * 8][tx] = x[((size_t)t * DIM_ + d0 + ty + i * 8) * HW_ + hw0 + tx];
    __syncthreads();
    int d = d0 + tx;
    float sc = 1.f + g_mod[t * 1536 + d];
    float sh = g_mod[t * 1536 + 768 + d];
    #pragma unroll
    for (int i = 0; i < 4; i++) {
        int hw = hw0 + ty + i * 8;
        int p = t * HW_ + hw;
        float sum = g_stats[p], sq = g_stats[THW_ + p];
        float mean = sum * (1.f / 768.f);
        float var = sq * (1.f / 768.f) - mean * mean;
        float rinv = rsqrtf(var + 1e-5f);
        g_h[(size_t)p * DIM_ + d] = __float2half((tile[tx][ty + i * 8] - mean) * rinv * sc + sh);
    }
}

// ===================== q/k LN + RoPE (k -> half), two-pass (R13 proven) ========
__global__ void k_qk(const float* __restrict__ qn_w, const float* __restrict__ qn_b,
                     const float* __restrict__ kn_w, const float* __restrict__ kn_b) {
    int gw = (blockIdx.x * blockDim.x + threadIdx.x) >> 5;
    int lane = threadIdx.x & 31;
    if (gw >= THW_ * HEADS_) return;
    int p = gw / HEADS_, head = gw % HEADS_;
    int t = p / HW_, hw = p % HW_;
    int hh = hw / RES_, ww = hw % RES_;
    float coord = (lane < 8) ? (float)t : (lane < 16) ? (float)hh : (float)ww;
    float inv = exp2f(-1.66096404744368f * (float)(lane & 7));
    float ang = coord * inv;
    float c = cosf(ang), s = sinf(ang);
    #pragma unroll
    for (int which = 0; which < 2; which++) {
        float* base = g_fused + (size_t)p * QKN_ + which * 768 + head * DH_;
        float x1 = 0.f, x2 = 0.f;
        if (lane < 24) { x1 = base[2 * lane]; x2 = base[2 * lane + 1]; }
        float sum = x1 + x2, sq = x1 * x1 + x2 * x2;
        #pragma unroll
        for (int o = 16; o; o >>= 1) {
            sum += __shfl_xor_sync(0xffffffffu, sum, o);
            sq  += __shfl_xor_sync(0xffffffffu, sq, o);
        }
        float mean = sum * (1.f / 48.f);
        float var = sq * (1.f / 48.f) - mean * mean;
        float rinv = rsqrtf(var + 1e-5f);
        if (lane < 24) {
            const float* w = which ? kn_w : qn_w;
            const float* b = which ? kn_b : qn_b;
            float y1 = (x1 - mean) * rinv * w[2 * lane]     + b[2 * lane];
            float y2 = (x2 - mean) * rinv * w[2 * lane + 1] + b[2 * lane + 1];
            float o1 = y1 * c - y2 * s;
            float o2 = y1 * s + y2 * c;
            if (which == 0) {
                o1 *= 0.14433756729740643f; o2 *= 0.14433756729740643f;
                base[2 * lane] = o1; base[2 * lane + 1] = o2;
            } else {
                *(__half2*)(g_kvh + (size_t)p * 1536 + head * DH_ + 2 * lane) =
                    __floats2half2_rn(o1, o2);
            }
        }
    }
}

// ==== attention: 4 neighbor-groups of 8 lanes (R13 proven); pk pre-multiplied ===
__global__ void k_attn() {
    int warp = threadIdx.x >> 5, lane = threadIdx.x & 31;
    int gw = blockIdx.x * 8 + warp;
    if (gw >= THW_ * HEADS_) return;
    int head = gw % HEADS_, p = gw / HEADS_;
    int hw = p % HW_;
    int h = hw / RES_, w = hw % RES_;
    int grp = lane >> 3, gl = lane & 7;

    __shared__ float ssc[8][80];
    __shared__ int spk[8][80];
    float* sc = ssc[warp];
    int* pk = spk[warp];
    int h0 = min(max(h - 2, 0), RES_ - 5);
    int w0 = min(max(w - 2, 0), RES_ - 5);
    for (int j = lane; j < NBR_; j += 32) {
        int a = j / 25, r = j % 25, cc = r / 5, e = r % 5;
        pk[j] = ((a * RES_ + h0 + cc) * RES_ + (w0 + e)) * 1536;   // pre-multiplied
    }
    __syncwarp();

    float qr[8];
    if (gl < 6) {
        float4 qv0 = *(const float4*)(g_fused + (size_t)p * QKN_ + head * DH_ + gl * 8);
        float4 qv1 = *(const float4*)(g_fused + (size_t)p * QKN_ + head * DH_ + gl * 8 + 4);
        qr[0] = qv0.x; qr[1] = qv0.y; qr[2] = qv0.z; qr[3] = qv0.w;
        qr[4] = qv1.x; qr[5] = qv1.y; qr[6] = qv1.z; qr[7] = qv1.w;
    }
    const __half* kbase = g_kvh + head * DH_ + gl * 8;
    const __half* vbase = kbase + 768;

    #pragma unroll 4
    for (int jb = 0; jb < 19; jb++) {
        int j = jb * 4 + grp;
        float partial = 0.f;
        if (j < NBR_ && gl < 6) {
            uint4 kv = *(const uint4*)(kbase + pk[j]);
            float2 f0 = __half22float2(*(__half2*)&kv.x);
            float2 f1 = __half22float2(*(__half2*)&kv.y);
            float2 f2 = __half22float2(*(__half2*)&kv.z);
            float2 f3 = __half22float2(*(__half2*)&kv.w);
            partial = qr[0] * f0.x + qr[1] * f0.y + qr[2] * f1.x + qr[3] * f1.y
                    + qr[4] * f2.x + qr[5] * f2.y + qr[6] * f3.x + qr[7] * f3.y;
        }
        partial += __shfl_xor_sync(0xffffffffu, partial, 1);
        partial += __shfl_xor_sync(0xffffffffu, partial, 2);
        partial += __shfl_xor_sync(0xffffffffu, partial, 4);
        if (gl == 0 && j < NBR_) sc[j] = partial;
    }
    __syncwarp();

    float m = -1e30f;
    for (int j = lane; j < NBR_; j += 32) m = fmaxf(m, sc[j]);
    #pragma unroll
    for (int o = 16; o; o >>= 1) m = fmaxf(m, __shfl_xor_sync(0xffffffffu, m, o));
    float sum = 0.f;
    for (int j = lane; j < NBR_; j += 32) {
        float e = __expf(sc[j] - m);
        sc[j] = e; sum += e;
    }
    #pragma unroll
    for (int o = 16; o; o >>= 1) sum += __shfl_xor_sync(0xffffffffu, sum, o);
    float rs = 1.f / sum;
    for (int j = lane; j < NBR_; j += 32) sc[j] *= rs;
    __syncwarp();

    float vacc[8] = {0.f, 0.f, 0.f, 0.f, 0.f, 0.f, 0.f, 0.f};
    #pragma unroll 4
    for (int jb = 0; jb < 19; jb++) {
        int j = jb * 4 + grp;
        if (j < NBR_ && gl < 6) {
            float pj = sc[j];
            uint4 vv = *(const uint4*)(vbase + pk[j]);
            float2 f0 = __half22float2(*(__half2*)&vv.x);
            float2 f1 = __half22float2(*(__half2*)&vv.y);
            float2 f2 = __half22float2(*(__half2*)&vv.z);
            float2 f3 = __half22float2(*(__half2*)&vv.w);
            vacc[0] += pj * f0.x; vacc[1] += pj * f0.y;
            vacc[2] += pj * f1.x; vacc[3] += pj * f1.y;
            vacc[4] += pj * f2.x; vacc[5] += pj * f2.y;
            vacc[6] += pj * f3.x; vacc[7] += pj * f3.y;
        }
    }
    #pragma unroll
    for (int d = 0; d < 8; d++) {
        vacc[d] += __shfl_xor_sync(0xffffffffu, vacc[d], 8);
        vacc[d] += __shfl_xor_sync(0xffffffffu, vacc[d], 16);
    }
    if (grp == 0 && gl < 6) {
        __half2 h0 = __floats2half2_rn(vacc[0], vacc[1]);
        __half2 h1 = __floats2half2_rn(vacc[2], vacc[3]);
        __half2 h2 = __floats2half2_rn(vacc[4], vacc[5]);
        __half2 h3 = __floats2half2_rn(vacc[6], vacc[7]);
        uint4 o = make_uint4(*(uint32_t*)&h0, *(uint32_t*)&h1,
                             *(uint32_t*)&h2, *(uint32_t*)&h3);
        *(uint4*)(g_afin + (size_t)p * KFIN_ + head * DH_ + gl * 8) = o;
    }
}

// ===================== launch =====================
extern "C" void kernel_launch(void* const* d_in, const int* in_sizes, int n_in,
                              void* d_out, int out_size) {
    const float* x       = (const float*)d_in[0];
    const float* emb     = (const float*)d_in[1];
    const float* w_mod   = (const float*)d_in[2];
    const float* b_mod   = (const float*)d_in[3];
    const float* qn_w    = (const float*)d_in[4];
    const float* qn_b    = (const float*)d_in[5];
    const float* kn_w    = (const float*)d_in[6];
    const float* kn_b    = (const float*)d_in[7];
    const float* W_fused = (const float*)d_in[8];
    const float* b_fused = (const float*)d_in[9];
    const float* W_out   = (const float*)d_in[10];
    const float* W_mlp   = (const float*)d_in[11];
    const float* b_mlp   = (const float*)d_in[12];
    float* out = (float*)d_out;

    __half* WF;    cudaGetSymbolAddress((void**)&WF, g_WF);
    __half* WFin;  cudaGetSymbolAddress((void**)&WFin, g_WFin);
    __half* gh;    cudaGetSymbolAddress((void**)&gh, g_h);
    float* gfused; cudaGetSymbolAddress((void**)&gfused, g_fused);
    __half* gkvh;  cudaGetSymbolAddress((void**)&gkvh, g_kvh);
    __half* gafin; cudaGetSymbolAddress((void**)&gafin, g_afin);
    float* gstats; cudaGetSymbolAddress((void**)&gstats, g_stats);

    const int smem1 = 3 * (128 * ROWH + 32 * ROWB) * 2;
    const int g2pipe = 3 * (32 * ROWH + 32 * ROWB) * 2;
    const int g2epi  = 128 * 33 * 4;
    const int smem2 = (g2pipe > g2epi) ? g2pipe : g2epi;
    cudaFuncSetAttribute(k_gemm<4, 0>, cudaFuncAttributeMaxDynamicSharedMemorySize, smem1);
    cudaFuncSetAttribute(k_gemm<1, 1>, cudaFuncAttributeMaxDynamicSharedMemorySize, smem2);

    cudaMemsetAsync(gstats, 0, 2 * THW_ * sizeof(float));
    k_prolog<<<NB_PRO, 256>>>(W_fused, W_out, W_mlp, emb, w_mod, b_mod, x);
    k_applyT<<<dim3(HW_ / 32, DIM_ / 32, T_), dim3(32, 8)>>>(x);
    // fused GEMM: 1728 x 5376, K=768 (q|k fp32, v half, silu(mlp) half)
    k_gemm<4, 0><<<dim3(FUSEDN_ / 128, 14), 256, smem1>>>(
        gh, DIM_, WF, FUSEDN_, DIM_, b_fused, gfused, gkvh, gafin, nullptr, nullptr);
    k_qk<<<(THW_ * HEADS_) / 8, 256>>>(qn_w, qn_b, kn_w, kn_b);
    k_attn<<<(THW_ * HEADS_) / 8, 256>>>();
    // final GEMM: 1728 x 768, K=3840, MT=1 -> 324 CTAs
    k_gemm<1, 1><<<dim3(DIM_ / 128, THW_ / 32), 256, smem2>>>(
        gafin, KFIN_, WFin, DIM_, KFIN_, b_mlp, nullptr, nullptr, nullptr, out, x);
}